// round 5
// baseline (speedup 1.0000x reference)
#include <cuda_runtime.h>
#include <cuda_bf16.h>
#include <cstdint>

// ---------------- problem constants ----------------
#define NI    512
#define NH    2048
#define NOUT  512
#define NROW  4096
#define MT    32      // rows per CTA
#define HC    128     // hidden cols per chunk
#define NHCNT 16      // hidden chunks
#define NK    8       // input chunks (= groups)
#define NTHR  512     // threads per CTA (16 warps)

// ---------------- smem layout (bytes) ----------------
#define XP     1040
#define XHALF  (32 * XP)          // 33280
#define OFF_X  0
#define W1P    144
#define W1HALF (128 * W1P)        // 18432
#define W1BUF  (2 * W1HALF)       // 36864
#define OFF_W1 (OFF_X + 2 * XHALF)        // 66560
#define W2P    272
#define W2HALF (64 * W2P)         // 17408
#define OFF_W2 (OFF_W1 + 2 * W1BUF)       // 140288
#define A2P    272
#define A2HALF (32 * A2P)         // 8704
#define OFF_A2 (OFF_W2 + 2 * W2HALF)      // 175104
#define SMEM_TOTAL (OFF_A2 + 2 * A2HALF)  // 192512

// ---------------- global bf16 hi/lo operands ----------------
__device__ __align__(16) __nv_bfloat16 g_xh[NROW * NI];
__device__ __align__(16) __nv_bfloat16 g_xl[NROW * NI];
__device__ __align__(16) __nv_bfloat16 g_w1h[NH * NI];    // [h][i] = W1^T
__device__ __align__(16) __nv_bfloat16 g_w1l[NH * NI];
__device__ __align__(16) __nv_bfloat16 g_w2h[NOUT * NH];  // [j][h] = W2^T
__device__ __align__(16) __nv_bfloat16 g_w2l[NOUT * NH];

// ---------------- PTX helpers (base sm_103 ISA only) ----------------
__device__ __forceinline__ uint32_t smem_u32(const void* p) {
    uint32_t a;
    asm("{ .reg .u64 t; cvta.to.shared.u64 t, %1; cvt.u32.u64 %0, t; }" : "=r"(a) : "l"(p));
    return a;
}
__device__ __forceinline__ void ldmx4(uint32_t* r, uint32_t a) {
    asm volatile("ldmatrix.sync.aligned.m8n8.x4.shared.b16 {%0,%1,%2,%3}, [%4];"
                 : "=r"(r[0]), "=r"(r[1]), "=r"(r[2]), "=r"(r[3]) : "r"(a));
}
__device__ __forceinline__ void ldmx2(uint32_t* r, uint32_t a) {
    asm volatile("ldmatrix.sync.aligned.m8n8.x2.shared.b16 {%0,%1}, [%2];"
                 : "=r"(r[0]), "=r"(r[1]) : "r"(a));
}
__device__ __forceinline__ void mmabf(float* c, const uint32_t* a, const uint32_t* b) {
    asm volatile("mma.sync.aligned.m16n8k16.row.col.f32.bf16.bf16.f32 "
                 "{%0,%1,%2,%3},{%4,%5,%6,%7},{%8,%9},{%0,%1,%2,%3};"
                 : "+f"(c[0]), "+f"(c[1]), "+f"(c[2]), "+f"(c[3])
                 : "r"(a[0]), "r"(a[1]), "r"(a[2]), "r"(a[3]), "r"(b[0]), "r"(b[1]));
}
__device__ __forceinline__ void cpa16(uint32_t s, const void* g) {
    asm volatile("cp.async.cg.shared.global [%0], [%1], 16;" :: "r"(s), "l"(g) : "memory");
}
#define CP_COMMIT() asm volatile("cp.async.commit_group;" ::: "memory")
#define CP_WAIT(n)  asm volatile("cp.async.wait_group %0;" :: "n"(n) : "memory")

__device__ __forceinline__ uint32_t pack_bf(float a, float b, float* lo_a, float* lo_b) {
    __nv_bfloat16 ha = __float2bfloat16_rn(a);
    __nv_bfloat16 hb = __float2bfloat16_rn(b);
    *lo_a = a - __bfloat162float(ha);
    *lo_b = b - __bfloat162float(hb);
    return ((uint32_t)__bfloat16_as_ushort(hb) << 16) | (uint32_t)__bfloat16_as_ushort(ha);
}
__device__ __forceinline__ uint32_t pack_lo(float a, float b) {
    return ((uint32_t)__bfloat16_as_ushort(__float2bfloat16_rn(b)) << 16)
         | (uint32_t)__bfloat16_as_ushort(__float2bfloat16_rn(a));
}

// ---------------- prep: fp32 -> bf16 hi/lo splits + transposes ----------------
__global__ void prep_split(const float* __restrict__ x,
                           const float* __restrict__ W1,
                           const float* __restrict__ W2) {
    int stride = gridDim.x * blockDim.x;
    for (int i = blockIdx.x * blockDim.x + threadIdx.x; i < NROW * NI; i += stride) {
        float v = x[i];
        __nv_bfloat16 h = __float2bfloat16_rn(v);
        g_xh[i] = h;
        g_xl[i] = __float2bfloat16_rn(v - __bfloat162float(h));
    }
    for (int i = blockIdx.x * blockDim.x + threadIdx.x; i < NI * NH; i += stride) {
        int r = i >> 11, h = i & (NH - 1);           // W1[r][h]
        float v = W1[i];
        __nv_bfloat16 hi = __float2bfloat16_rn(v);
        g_w1h[h * NI + r] = hi;
        g_w1l[h * NI + r] = __float2bfloat16_rn(v - __bfloat162float(hi));
    }
    for (int i = blockIdx.x * blockDim.x + threadIdx.x; i < NH * NOUT; i += stride) {
        int h = i >> 9, j = i & (NOUT - 1);          // W2[h][j]
        float v = W2[i];
        __nv_bfloat16 hi = __float2bfloat16_rn(v);
        g_w2h[j * NH + h] = hi;
        g_w2l[j * NH + h] = __float2bfloat16_rn(v - __bfloat162float(hi));
    }
}

// ---------------- staged loaders (512 threads) ----------------
__device__ __forceinline__ void load_w1(uint32_t sb, int hc, int k, int buf, int tid) {
#pragma unroll
    for (int q = 0; q < 4; ++q) {
        int idx = tid + NTHR * q;                    // 0..2047
        int arr = idx >> 10, rem = idx & 1023;
        int h = rem >> 3, ch = rem & 7;
        const __nv_bfloat16* g = (arr ? g_w1l : g_w1h) + (size_t)(hc * HC + h) * NI + k * 64 + ch * 8;
        cpa16(sb + OFF_W1 + buf * W1BUF + arr * W1HALF + h * W1P + ch * 16, g);
    }
}
__device__ __forceinline__ void load_w2(uint32_t sb, int hc, int g, int tid) {
#pragma unroll
    for (int q = 0; q < 4; ++q) {
        int idx = tid + NTHR * q;
        int arr = idx >> 10, rem = idx & 1023;
        int j = rem >> 4, ch = rem & 15;
        const __nv_bfloat16* gp = (arr ? g_w2l : g_w2h) + (size_t)(g * 64 + j) * NH + hc * HC + ch * 8;
        cpa16(sb + OFF_W2 + arr * W2HALF + j * W2P + ch * 16, gp);
    }
}

// ---------------- main kernel ----------------
__global__ void __launch_bounds__(NTHR, 1)
adjnet_mma_kernel(const float* __restrict__ b1,
                  const float* __restrict__ b2,
                  float* __restrict__ out) {
    extern __shared__ char sm[];
    const uint32_t sb = smem_u32(sm);
    const int tid = threadIdx.x;
    const int lane = tid & 31;
    const int wid = tid >> 5;                // 0..15
    const int mi = wid & 1;                  // m half (16 rows)
    const int nj = wid >> 1;                 // 0..7
    const int row0 = blockIdx.x * MT;

    // ---- prologue loads: resident x (hi+lo) + W1 chunk 0 ----
#pragma unroll
    for (int q = 0; q < 8; ++q) {
        int idx = tid + NTHR * q;            // 0..4095
        int arr = idx >> 11, rem = idx & 2047;
        int r = rem >> 6, ch = rem & 63;
        const __nv_bfloat16* g = (arr ? g_xl : g_xh) + (size_t)(row0 + r) * NI + ch * 8;
        cpa16(sb + OFF_X + arr * XHALF + r * XP + ch * 16, g);
    }
    CP_COMMIT();
    load_w1(sb, 0, 0, 0, tid);
    CP_COMMIT();

    // ---- per-thread fragment addresses ----
    const int lr = lane & 15;                 // a-frag row lane
    const int lc = (lane >> 4) << 3;          // a-frag col block (elements)
    const uint32_t aX  = sb + OFF_X  + (mi * 16 + lr) * XP  + lc * 2;
    const uint32_t aA2 = sb + OFF_A2 + (mi * 16 + lr) * A2P + lc * 2;
    const int bn = lane & 7;                  // b-frag row lane
    const int bk = ((lane >> 3) & 1) << 3;    // b-frag k block (elements)
    const uint32_t bW1 = sb + OFF_W1 + (nj * 16 + bn) * W1P + bk * 2;
    const uint32_t bW2 = sb + OFF_W2 + (nj * 8  + bn) * W2P + bk * 2;
    const int sr = lane >> 2;                 // c-frag row
    const int sc = (lane & 3) * 2;            // c-frag col
    const int stA2 = OFF_A2 + (mi * 16 + sr) * A2P;   // byte offset (char* based)

    float D[NK][4];
#pragma unroll
    for (int g = 0; g < NK; ++g)
#pragma unroll
        for (int e = 0; e < 4; ++e) D[g][e] = 0.f;

#pragma unroll 1
    for (int hc = 0; hc < NHCNT; ++hc) {
        float S[2][4];
#pragma unroll
        for (int s = 0; s < 2; ++s)
#pragma unroll
            for (int e = 0; e < 4; ++e) S[s][e] = 0.f;

        float bias[4];
#pragma unroll
        for (int s = 0; s < 2; ++s) {
            float2 bv = *reinterpret_cast<const float2*>(b1 + hc * HC + nj * 16 + s * 8 + sc);
            bias[2 * s] = bv.x; bias[2 * s + 1] = bv.y;
        }

#pragma unroll 1
        for (int k = 0; k < NK; ++k) {
            const int it = hc * NK + k;
            // stage W2 (current) and W1 (next)
            load_w2(sb, hc, k, tid);
            CP_COMMIT();
            const int itn = (it + 1) & 127;
            load_w1(sb, itn >> 3, itn & 7, (it + 1) & 1, tid);
            CP_COMMIT();
            CP_WAIT(2);                       // W1(cur) + everything older done
            __syncthreads();

            // ---- GEMM1: S += x[:, k*64 : k*64+64] @ W1chunk (3 passes) ----
            const uint32_t w1b = bW1 + (it & 1) * W1BUF;
#pragma unroll
            for (int kk = 0; kk < 4; ++kk) {
                uint32_t ah[4], al[4];
                ldmx4(ah, aX + (k * 64 + kk * 16) * 2);
                ldmx4(al, aX + XHALF + (k * 64 + kk * 16) * 2);
#pragma unroll
                for (int s = 0; s < 2; ++s) {
                    uint32_t bh[2], bl[2];
                    ldmx2(bh, w1b + s * 8 * W1P + kk * 32);
                    ldmx2(bl, w1b + W1HALF + s * 8 * W1P + kk * 32);
                    mmabf(S[s], ah, bh);
                    mmabf(S[s], ah, bl);
                    mmabf(S[s], al, bh);
                }
            }

            // ---- snapshot: relu(S + b1) -> A2 hi/lo (group k's activation) ----
#pragma unroll
            for (int s = 0; s < 2; ++s) {
                float v0 = fmaxf(S[s][0] + bias[2 * s],     0.f);
                float v1 = fmaxf(S[s][1] + bias[2 * s + 1], 0.f);
                float v2 = fmaxf(S[s][2] + bias[2 * s],     0.f);
                float v3 = fmaxf(S[s][3] + bias[2 * s + 1], 0.f);
                const int cb = (nj * 16 + s * 8 + sc) * 2;    // byte col
                float l0, l1, l2, l3;
                uint32_t p01 = pack_bf(v0, v1, &l0, &l1);
                uint32_t p23 = pack_bf(v2, v3, &l2, &l3);
                *reinterpret_cast<uint32_t*>(sm + stA2 + cb)                    = p01;
                *reinterpret_cast<uint32_t*>(sm + stA2 + 8 * A2P + cb)          = p23;
                *reinterpret_cast<uint32_t*>(sm + stA2 + A2HALF + cb)           = pack_lo(l0, l1);
                *reinterpret_cast<uint32_t*>(sm + stA2 + A2HALF + 8 * A2P + cb) = pack_lo(l2, l3);
            }
            CP_WAIT(1);                       // W2(cur) done (W1 next may be in flight)
            __syncthreads();

            // ---- GEMM2: D[k] += relu_tile @ W2[hc chunk, group k cols] (3 passes) ----
#pragma unroll
            for (int kk = 0; kk < 8; ++kk) {
                uint32_t ah[4], al[4];
                ldmx4(ah, aA2 + kk * 32);
                ldmx4(al, aA2 + A2HALF + kk * 32);
                uint32_t bh[2], bl[2];
                ldmx2(bh, bW2 + kk * 32);
                ldmx2(bl, bW2 + W2HALF + kk * 32);
                mmabf(D[k], ah, bh);
                mmabf(D[k], ah, bl);
                mmabf(D[k], al, bh);
            }
            __syncthreads();                  // protect A2 / W2 before next stage
        }
    }

    // ---- epilogue: out = D + b2 ----
#pragma unroll
    for (int g = 0; g < NK; ++g) {
        const int col = g * 64 + nj * 8 + sc;
        const int r = row0 + mi * 16 + sr;
        float2 bv = *reinterpret_cast<const float2*>(b2 + col);
        float2 o0, o1;
        o0.x = D[g][0] + bv.x; o0.y = D[g][1] + bv.y;
        o1.x = D[g][2] + bv.x; o1.y = D[g][3] + bv.y;
        *reinterpret_cast<float2*>(out + (size_t)r * NOUT + col)       = o0;
        *reinterpret_cast<float2*>(out + (size_t)(r + 8) * NOUT + col) = o1;
    }
}

// ---------------- launch ----------------
extern "C" void kernel_launch(void* const* d_in, const int* in_sizes, int n_in,
                              void* d_out, int out_size)
{
    const float* x  = (const float*)d_in[0];   // (4096, 512)
    const float* W1 = (const float*)d_in[1];   // (512, 2048)
    const float* b1 = (const float*)d_in[2];   // (2048,)
    const float* W2 = (const float*)d_in[3];   // (2048, 512)
    const float* b2 = (const float*)d_in[4];   // (512,)
    float* out = (float*)d_out;                // (4096, 512)

    cudaFuncSetAttribute(adjnet_mma_kernel,
                         cudaFuncAttributeMaxDynamicSharedMemorySize, SMEM_TOTAL);

    prep_split<<<1024, 256>>>(x, W1, W2);
    adjnet_mma_kernel<<<NROW / MT, NTHR, SMEM_TOTAL>>>(b1, b2, out);
}

// round 6
// speedup vs baseline: 1.4081x; 1.4081x over previous
#include <cuda_runtime.h>
#include <cuda_bf16.h>
#include <cstdint>

// ---------------- problem constants ----------------
#define NI    512
#define NH    2048
#define NOUT  512
#define NROW  4096
#define MT    32
#define NTHR  256
#define NITER 128     // 16 hc chunks x 8 k chunks

// ---------------- smem layout ----------------
// x chunk:  [32 r][64+8 el] pitch 144, hi+lo, 2 bufs
#define XCP    144
#define XCARR  (32 * XCP)         // 4608
#define XCBUF  (2 * XCARR)        // 9216
#define OFF_XC 0
// W1 chunk (natural [64 k][128 h]): pitch 272, hi+lo, 2 bufs
#define W1P    272
#define W1ARR  (64 * W1P)         // 17408
#define W1BUF  (2 * W1ARR)        // 34816
#define OFF_W1 (OFF_XC + 2 * XCBUF)       // 18432
// W2 chunk (natural [128 h][64 j]): pitch 144, hi+lo, 2 bufs
#define W2P    144
#define W2ARR  (128 * W2P)        // 18432
#define W2BUF  (2 * W2ARR)        // 36864
#define OFF_W2 (OFF_W1 + 2 * W1BUF)       // 88064
// A2 snapshot [32 r][128 h] pitch 272, hi+lo, 2 bufs
#define A2P    272
#define A2ARR  (32 * A2P)         // 8704
#define A2BUF  (2 * A2ARR)        // 17408
#define OFF_A2 (OFF_W2 + 2 * W2BUF)       // 161792
#define SMEM_TOTAL (OFF_A2 + 2 * A2BUF)   // 196608

// ---------------- global bf16 hi/lo operands (all natural layout) ----------
__device__ __align__(16) __nv_bfloat16 g_xh[NROW * NI];
__device__ __align__(16) __nv_bfloat16 g_xl[NROW * NI];
__device__ __align__(16) __nv_bfloat16 g_w1h[NI * NH];    // [i][h]
__device__ __align__(16) __nv_bfloat16 g_w1l[NI * NH];
__device__ __align__(16) __nv_bfloat16 g_w2h[NH * NOUT];  // [h][j]
__device__ __align__(16) __nv_bfloat16 g_w2l[NH * NOUT];

// ---------------- PTX helpers ----------------
__device__ __forceinline__ uint32_t smem_u32(const void* p) {
    uint32_t a;
    asm("{ .reg .u64 t; cvta.to.shared.u64 t, %1; cvt.u32.u64 %0, t; }" : "=r"(a) : "l"(p));
    return a;
}
__device__ __forceinline__ void ldmx4(uint32_t* r, uint32_t a) {
    asm volatile("ldmatrix.sync.aligned.m8n8.x4.shared.b16 {%0,%1,%2,%3}, [%4];"
                 : "=r"(r[0]), "=r"(r[1]), "=r"(r[2]), "=r"(r[3]) : "r"(a));
}
__device__ __forceinline__ void ldmx4t(uint32_t* r, uint32_t a) {
    asm volatile("ldmatrix.sync.aligned.m8n8.x4.trans.shared.b16 {%0,%1,%2,%3}, [%4];"
                 : "=r"(r[0]), "=r"(r[1]), "=r"(r[2]), "=r"(r[3]) : "r"(a));
}
__device__ __forceinline__ void mmabf(float* c, const uint32_t* a, const uint32_t* b) {
    asm volatile("mma.sync.aligned.m16n8k16.row.col.f32.bf16.bf16.f32 "
                 "{%0,%1,%2,%3},{%4,%5,%6,%7},{%8,%9},{%0,%1,%2,%3};"
                 : "+f"(c[0]), "+f"(c[1]), "+f"(c[2]), "+f"(c[3])
                 : "r"(a[0]), "r"(a[1]), "r"(a[2]), "r"(a[3]), "r"(b[0]), "r"(b[1]));
}
__device__ __forceinline__ void cpa16(uint32_t s, const void* g) {
    asm volatile("cp.async.cg.shared.global [%0], [%1], 16;" :: "r"(s), "l"(g) : "memory");
}
#define CP_COMMIT() asm volatile("cp.async.commit_group;" ::: "memory")
#define CP_WAIT(n)  asm volatile("cp.async.wait_group %0;" :: "n"(n) : "memory")

__device__ __forceinline__ uint32_t pack_bf(float a, float b, float* lo_a, float* lo_b) {
    __nv_bfloat16 ha = __float2bfloat16_rn(a);
    __nv_bfloat16 hb = __float2bfloat16_rn(b);
    *lo_a = a - __bfloat162float(ha);
    *lo_b = b - __bfloat162float(hb);
    return ((uint32_t)__bfloat16_as_ushort(hb) << 16) | (uint32_t)__bfloat16_as_ushort(ha);
}
__device__ __forceinline__ uint32_t pack_lo(float a, float b) {
    return ((uint32_t)__bfloat16_as_ushort(__float2bfloat16_rn(b)) << 16)
         | (uint32_t)__bfloat16_as_ushort(__float2bfloat16_rn(a));
}

// ---------------- prep: pure streaming hi/lo split (all coalesced) --------
__global__ void prep_split(const float* __restrict__ x,
                           const float* __restrict__ W1,
                           const float* __restrict__ W2) {
    int stride = gridDim.x * blockDim.x;
    for (int i = blockIdx.x * blockDim.x + threadIdx.x; i < NROW * NI; i += stride) {
        float v = x[i];
        __nv_bfloat16 h = __float2bfloat16_rn(v);
        g_xh[i] = h;
        g_xl[i] = __float2bfloat16_rn(v - __bfloat162float(h));
    }
    for (int i = blockIdx.x * blockDim.x + threadIdx.x; i < NI * NH; i += stride) {
        float v = W1[i];
        __nv_bfloat16 h = __float2bfloat16_rn(v);
        g_w1h[i] = h;
        g_w1l[i] = __float2bfloat16_rn(v - __bfloat162float(h));
    }
    for (int i = blockIdx.x * blockDim.x + threadIdx.x; i < NH * NOUT; i += stride) {
        float v = W2[i];
        __nv_bfloat16 h = __float2bfloat16_rn(v);
        g_w2h[i] = h;
        g_w2l[i] = __float2bfloat16_rn(v - __bfloat162float(h));
    }
}

// ---------------- staged loaders (256 threads) ----------------
__device__ __forceinline__ void load_xc(uint32_t sb, int k, int buf, int row0, int tid) {
#pragma unroll
    for (int q = 0; q < 2; ++q) {
        int idx = tid + NTHR * q;            // 0..511
        int arr = idx >> 8, rem = idx & 255;
        int r = rem >> 3, c = rem & 7;
        const __nv_bfloat16* g = (arr ? g_xl : g_xh) + (size_t)(row0 + r) * NI + k * 64 + c * 8;
        cpa16(sb + OFF_XC + buf * XCBUF + arr * XCARR + r * XCP + c * 16, g);
    }
}
__device__ __forceinline__ void load_w1(uint32_t sb, int hc, int k, int buf, int tid) {
#pragma unroll
    for (int q = 0; q < 8; ++q) {
        int idx = tid + NTHR * q;            // 0..2047
        int arr = idx >> 10, rem = idx & 1023;
        int r = rem >> 4, c = rem & 15;      // r: k-row 0..63, c: 16B chunk over 128 h
        const __nv_bfloat16* g = (arr ? g_w1l : g_w1h) + (size_t)(k * 64 + r) * NH + hc * 128 + c * 8;
        cpa16(sb + OFF_W1 + buf * W1BUF + arr * W1ARR + r * W1P + c * 16, g);
    }
}
__device__ __forceinline__ void load_w2(uint32_t sb, int hc, int grp, int buf, int tid) {
#pragma unroll
    for (int q = 0; q < 8; ++q) {
        int idx = tid + NTHR * q;            // 0..2047
        int arr = idx >> 10, rem = idx & 1023;
        int r = rem >> 3, c = rem & 7;       // r: h-row 0..127, c: chunk over 64 j
        const __nv_bfloat16* g = (arr ? g_w2l : g_w2h) + (size_t)(hc * 128 + r) * NOUT + grp * 64 + c * 8;
        cpa16(sb + OFF_W2 + buf * W2BUF + arr * W2ARR + r * W2P + c * 16, g);
    }
}

// ---------------- main kernel ----------------
__global__ void __launch_bounds__(NTHR, 1)
adjnet_mma_kernel(const float* __restrict__ b1,
                  const float* __restrict__ b2,
                  float* __restrict__ out) {
    extern __shared__ char sm[];
    const uint32_t sb = smem_u32(sm);
    const int tid = threadIdx.x;
    const int lane = tid & 31;
    const int wid = tid >> 5;                // 0..7
    const int mi = wid & 1;                  // m half
    const int nj = wid >> 1;                 // 0..3
    const int row0 = blockIdx.x * MT;

    // ---- pipeline bootstrap: P0, Q0, P1 ----
    load_xc(sb, 0, 0, row0, tid); load_w1(sb, 0, 0, 0, tid); CP_COMMIT();   // P0
    load_w2(sb, 0, 0, 0, tid); CP_COMMIT();                                  // Q0
    load_xc(sb, 1, 1, row0, tid); load_w1(sb, 0, 1, 1, tid); CP_COMMIT();   // P1

    // ---- per-lane fragment addressing ----
    const int lr = lane & 15;
    const uint32_t aoffX  = (uint32_t)((mi * 16 + lr) * XCP + (lane >> 4) * 16);
    const uint32_t aoffA2 = (uint32_t)((mi * 16 + lr) * A2P + (lane >> 4) * 16);
    const int m = lane >> 3, rw = lane & 7;
    // B (trans) lane offsets: row = (m&1)*8+rw within 16-k block; col = n-tile
    const uint32_t boff1 = (uint32_t)(((m & 1) * 8 + rw) * W1P + (nj * 32 + (m >> 1) * 8) * 2);
    const uint32_t boff2 = (uint32_t)(((m & 1) * 8 + rw) * W2P + (nj * 16 + (m >> 1) * 8) * 2);
    const int sr = lane >> 2;
    const int sc = (lane & 3) * 2;

    float D[8][2][4];
#pragma unroll
    for (int g = 0; g < 8; ++g)
#pragma unroll
        for (int s = 0; s < 2; ++s)
#pragma unroll
            for (int e = 0; e < 4; ++e) D[g][s][e] = 0.f;

    CP_WAIT(2);                 // P0 done (Q0, P1 may be in flight)
    __syncthreads();

#pragma unroll 1
    for (int hc = 0; hc < 16; ++hc) {
        float S[4][4];
        float bias[8];
#pragma unroll
        for (int s = 0; s < 4; ++s) {
#pragma unroll
            for (int e = 0; e < 4; ++e) S[s][e] = 0.f;
            float2 bv = *reinterpret_cast<const float2*>(b1 + hc * 128 + nj * 32 + s * 8 + sc);
            bias[2 * s] = bv.x; bias[2 * s + 1] = bv.y;
        }

#pragma unroll
        for (int k = 0; k < 8; ++k) {
            const int it = hc * 8 + k;
            const int pb = k & 1;            // == it & 1

            // ---- A: GEMM1  S += x_chunk @ W1chunk (3-pass) ----
            const uint32_t xb  = sb + OFF_XC + pb * XCBUF + aoffX;
            const uint32_t w1b = sb + OFF_W1 + pb * W1BUF + boff1;
#pragma unroll
            for (int kk = 0; kk < 4; ++kk) {
                uint32_t ah[4], al[4], bh0[4], bh1[4], bl0[4], bl1[4];
                ldmx4 (ah,  xb + kk * 32);
                ldmx4 (al,  xb + XCARR + kk * 32);
                ldmx4t(bh0, w1b + kk * (16 * W1P));
                ldmx4t(bh1, w1b + kk * (16 * W1P) + 32);
                ldmx4t(bl0, w1b + W1ARR + kk * (16 * W1P));
                ldmx4t(bl1, w1b + W1ARR + kk * (16 * W1P) + 32);
                mmabf(S[0], ah, bh0);     mmabf(S[0], ah, bl0);     mmabf(S[0], al, bh0);
                mmabf(S[1], ah, bh0 + 2); mmabf(S[1], ah, bl0 + 2); mmabf(S[1], al, bh0 + 2);
                mmabf(S[2], ah, bh1);     mmabf(S[2], ah, bl1);     mmabf(S[2], al, bh1);
                mmabf(S[3], ah, bh1 + 2); mmabf(S[3], ah, bl1 + 2); mmabf(S[3], al, bh1 + 2);
            }

            // ---- B: snapshot relu(S + b1) -> A2[pb] hi/lo ----
            {
                char* bA = sm + OFF_A2 + pb * A2BUF + (mi * 16 + sr) * A2P;
#pragma unroll
                for (int s = 0; s < 4; ++s) {
                    float v0 = fmaxf(S[s][0] + bias[2 * s],     0.f);
                    float v1 = fmaxf(S[s][1] + bias[2 * s + 1], 0.f);
                    float v2 = fmaxf(S[s][2] + bias[2 * s],     0.f);
                    float v3 = fmaxf(S[s][3] + bias[2 * s + 1], 0.f);
                    const int cb = (nj * 32 + s * 8 + sc) * 2;
                    float l0, l1, l2, l3;
                    uint32_t p01 = pack_bf(v0, v1, &l0, &l1);
                    uint32_t p23 = pack_bf(v2, v3, &l2, &l3);
                    *reinterpret_cast<uint32_t*>(bA + cb)                    = p01;
                    *reinterpret_cast<uint32_t*>(bA + 8 * A2P + cb)          = p23;
                    *reinterpret_cast<uint32_t*>(bA + A2ARR + cb)            = pack_lo(l0, l1);
                    *reinterpret_cast<uint32_t*>(bA + A2ARR + 8 * A2P + cb)  = pack_lo(l2, l3);
                }
            }
            __syncthreads();     // C: separates A2/W-buf readers from new writes

            // ---- D: prefetch  Q_{it+1} (W2), P_{it+2} (x,W1) ----
            {
                const int itq = it + 1;
                if (itq < NITER) load_w2(sb, itq >> 3, itq & 7, itq & 1, tid);
                CP_COMMIT();
                const int itp = it + 2;
                if (itp < NITER) {
                    load_xc(sb, itp & 7, itp & 1, row0, tid);
                    load_w1(sb, itp >> 3, itp & 7, itp & 1, tid);
                }
                CP_COMMIT();
            }
            CP_WAIT(2);          // E: all but the 2 just-issued groups done
            __syncthreads();     // F

            // ---- G: GEMM2  D[k] += relu_tile @ W2 (3-pass) ----
            const uint32_t a2b = sb + OFF_A2 + pb * A2BUF + aoffA2;
            const uint32_t w2b = sb + OFF_W2 + pb * W2BUF + boff2;
#pragma unroll
            for (int kk = 0; kk < 8; ++kk) {
                uint32_t ah[4], al[4], bh[4], bl[4];
                ldmx4 (ah, a2b + kk * 32);
                ldmx4 (al, a2b + A2ARR + kk * 32);
                ldmx4t(bh, w2b + kk * (16 * W2P));
                ldmx4t(bl, w2b + W2ARR + kk * (16 * W2P));
                mmabf(D[k][0], ah, bh);     mmabf(D[k][0], ah, bl);     mmabf(D[k][0], al, bh);
                mmabf(D[k][1], ah, bh + 2); mmabf(D[k][1], ah, bl + 2); mmabf(D[k][1], al, bh + 2);
            }
        }
    }

    // ---- epilogue: out = D + b2 ----
#pragma unroll
    for (int g = 0; g < 8; ++g) {
#pragma unroll
        for (int s = 0; s < 2; ++s) {
            const int col = g * 64 + nj * 16 + s * 8 + sc;
            const int r = row0 + mi * 16 + sr;
            float2 bv = *reinterpret_cast<const float2*>(b2 + col);
            float2 o0, o1;
            o0.x = D[g][s][0] + bv.x; o0.y = D[g][s][1] + bv.y;
            o1.x = D[g][s][2] + bv.x; o1.y = D[g][s][3] + bv.y;
            *reinterpret_cast<float2*>(out + (size_t)r * NOUT + col)       = o0;
            *reinterpret_cast<float2*>(out + (size_t)(r + 8) * NOUT + col) = o1;
        }
    }
}

// ---------------- launch ----------------
extern "C" void kernel_launch(void* const* d_in, const int* in_sizes, int n_in,
                              void* d_out, int out_size)
{
    const float* x  = (const float*)d_in[0];   // (4096, 512)
    const float* W1 = (const float*)d_in[1];   // (512, 2048)
    const float* b1 = (const float*)d_in[2];   // (2048,)
    const float* W2 = (const float*)d_in[3];   // (2048, 512)
    const float* b2 = (const float*)d_in[4];   // (512,)
    float* out = (float*)d_out;                // (4096, 512)

    cudaFuncSetAttribute(adjnet_mma_kernel,
                         cudaFuncAttributeMaxDynamicSharedMemorySize, SMEM_TOTAL);

    prep_split<<<1024, 256>>>(x, W1, W2);
    adjnet_mma_kernel<<<NROW / MT, NTHR, SMEM_TOTAL>>>(b1, b2, out);
}